// round 15
// baseline (speedup 1.0000x reference)
#include <cuda_runtime.h>

#define NT 128
#define BB 256
#define SS 512

__device__ float g_part[BB];
__device__ float g_gold[BB];

// ---- packed fp32x2 helpers (sm_100+; ptxas never auto-fuses these) ----
__device__ __forceinline__ unsigned long long pack2(float lo, float hi) {
    unsigned long long r;
    asm("mov.b64 %0, {%1, %2};" : "=l"(r) : "f"(lo), "f"(hi));
    return r;
}
#define FMA2(acc, a, b) \
    asm("fma.rn.f32x2 %0, %1, %2, %0;" : "+l"(acc) : "l"(a), "l"(b))
__device__ __forceinline__ float hadd2(unsigned long long a) {
    float lo, hi;
    asm("mov.b64 {%0, %1}, %2;" : "=f"(lo), "=f"(hi) : "l"(a));
    return lo + hi;
}

// One CTA per PAIR of batches, split-K matvec, ONE block barrier per step.
// eTp registers (exp(T) sub-block) are shared by both batch recurrences; the
// two serial chains interleave so each covers the other's latency. Warp w's
// i-slice [32w,32w+32) is produced by warp w's own threads -> v exchange is
// intra-warp (STS + syncwarp + LDS.128).
__global__ __launch_bounds__(128, 1) void crf_forward_kernel(
    const float* __restrict__ emissions,      // [B, S, NT]
    const void* __restrict__ tags_raw,        // [B, S] int32 or int64
    const void* __restrict__ mask_raw,        // [B, S] 1B or 4B bool
    const float* __restrict__ trans)          // [NT, NT]
{
    const int bA = 2 * blockIdx.x;
    const int bB = bA + 1;
    const int j = threadIdx.x;
    const int lane = j & 31;
    const int wid = j >> 5;

    __shared__ __align__(16) float vshwA[4][32];
    __shared__ __align__(16) float vshwB[4][32];
    __shared__ __align__(16) float pshA[2][4][NT];
    __shared__ __align__(16) float pshB[2][4][NT];
    __shared__ float mshA[2], mshB[2];
    __shared__ float warpred[4];
    __shared__ float warpsum[4];
    __shared__ int sh_tags64, sh_mask4;

    // ---- dtype detection (JAX x64-off silently makes int64 -> int32) ----
    if (j == 0) {
        const unsigned int* tw = (const unsigned int*)tags_raw;
        int is64 = 1;
        for (int k = 0; k < 32; k++)
            if (tw[2 * k + 1] != 0u) is64 = 0;
        sh_tags64 = is64;
        unsigned int w0 = ((const unsigned int*)mask_raw)[0];
        sh_mask4 = (w0 & 0xFFFFFF00u) ? 0 : 1;
    }

    // ---- eTp[oi][k]: packed exp(T) for my i-slice x 4 output columns ----
    const int ibase = wid * 32;
    unsigned long long eTp[4][16];
#pragma unroll
    for (int oi = 0; oi < 4; oi++) {
        const int col = lane + 32 * oi;
#pragma unroll
        for (int k = 0; k < 16; k++)
            eTp[oi][k] = pack2(__expf(trans[(ibase + 2 * k) * NT + col]),
                               __expf(trans[(ibase + 2 * k + 1) * NT + col]));
    }

    const float* eAp = emissions + (size_t)bA * SS * NT;
    const float* eBp = emissions + (size_t)bB * SS * NT;
    float alphaA0 = eAp[j];
    float alphaB0 = eBp[j];

    if (j == 0) { mshA[0] = alphaA0; mshB[0] = alphaB0; }
    __syncthreads();
    const float a0A = mshA[0];
    const float a0B = mshB[0];

    float vA = __expf(alphaA0 - a0A);
    float vB = __expf(alphaB0 - a0B);
    float sA_prev = a0A, sB_prev = a0B;

    // ---- prologue: warp-local exchange of v_0 + phase A -> psh[0] ----
    vshwA[wid][lane] = vA;
    vshwB[wid][lane] = vB;
    __syncwarp();
    {
        unsigned long long cA0 = 0ull, cA1 = 0ull, cA2 = 0ull, cA3 = 0ull;
        unsigned long long cB0 = 0ull, cB1 = 0ull, cB2 = 0ull, cB3 = 0ull;
        const ulonglong2* v2A = (const ulonglong2*)vshwA[wid];
        const ulonglong2* v2B = (const ulonglong2*)vshwB[wid];
#pragma unroll
        for (int k2 = 0; k2 < 8; k2++) {
            ulonglong2 qA = v2A[k2];
            ulonglong2 qB = v2B[k2];
            FMA2(cA0, qA.x, eTp[0][2 * k2]);
            FMA2(cB0, qB.x, eTp[0][2 * k2]);
            FMA2(cA1, qA.x, eTp[1][2 * k2]);
            FMA2(cB1, qB.x, eTp[1][2 * k2]);
            FMA2(cA2, qA.x, eTp[2][2 * k2]);
            FMA2(cB2, qB.x, eTp[2][2 * k2]);
            FMA2(cA3, qA.x, eTp[3][2 * k2]);
            FMA2(cB3, qB.x, eTp[3][2 * k2]);
            FMA2(cA0, qA.y, eTp[0][2 * k2 + 1]);
            FMA2(cB0, qB.y, eTp[0][2 * k2 + 1]);
            FMA2(cA1, qA.y, eTp[1][2 * k2 + 1]);
            FMA2(cB1, qB.y, eTp[1][2 * k2 + 1]);
            FMA2(cA2, qA.y, eTp[2][2 * k2 + 1]);
            FMA2(cB2, qB.y, eTp[2][2 * k2 + 1]);
            FMA2(cA3, qA.y, eTp[3][2 * k2 + 1]);
            FMA2(cB3, qB.y, eTp[3][2 * k2 + 1]);
        }
        pshA[0][wid][lane +  0] = hadd2(cA0);
        pshA[0][wid][lane + 32] = hadd2(cA1);
        pshA[0][wid][lane + 64] = hadd2(cA2);
        pshA[0][wid][lane + 96] = hadd2(cA3);
        pshB[0][wid][lane +  0] = hadd2(cB0);
        pshB[0][wid][lane + 32] = hadd2(cB1);
        pshB[0][wid][lane + 64] = hadd2(cB2);
        pshB[0][wid][lane + 96] = hadd2(cB3);
    }

    // depth-2 emission prefetch for both batches
    float eA_cur = eAp[NT + j], eA_n1 = eAp[2 * NT + j];
    float eB_cur = eBp[NT + j], eB_n1 = eBp[2 * NT + j];
    eAp += 3 * NT; eBp += 3 * NT;

    float wA = 0.f, sA_used = 0.f, eA_used = 0.f;
    float wB = 0.f, sB_used = 0.f, eB_used = 0.f;

    // ---- forward recursion, 511 steps; ONE __syncthreads per step ----
    int pbuf = 0;
    for (int t = 1; t < SS; t++) {
        float eA_n2 = 0.f, eB_n2 = 0.f;
        if (t + 2 < SS) {
            eA_n2 = eAp[j]; eAp += NT;
            eB_n2 = eBp[j]; eBp += NT;
        }

        __syncthreads();               // psh[pbuf]/msh[pbuf] visible

        // phase B for both batches
        float wa = (pshA[pbuf][0][j] + pshA[pbuf][1][j]) +
                   (pshA[pbuf][2][j] + pshA[pbuf][3][j]);
        float wb = (pshB[pbuf][0][j] + pshB[pbuf][1][j]) +
                   (pshB[pbuf][2][j] + pshB[pbuf][3][j]);
        wA = wa; wB = wb;
        float sA_new = mshA[pbuf];
        float sB_new = mshB[pbuf];
        float vA_new = wa * __expf((sA_prev - sA_new) + eA_cur);
        float vB_new = wb * __expf((sB_prev - sB_new) + eB_cur);

        float aA_next = 0.f, aB_next = 0.f;
        if (j == 0) {                  // next shifts; slack until next BAR
            aA_next = sA_prev + __logf(wa) + eA_cur;
            aB_next = sB_prev + __logf(wb) + eB_cur;
        }

        // warp-local v exchange (intra-warp only)
        vshwA[wid][lane] = vA_new;
        vshwB[wid][lane] = vB_new;
        __syncwarp();

        // phase A: partials of next w, both batches interleaved
        unsigned long long cA0 = 0ull, cA1 = 0ull, cA2 = 0ull, cA3 = 0ull;
        unsigned long long cB0 = 0ull, cB1 = 0ull, cB2 = 0ull, cB3 = 0ull;
        const ulonglong2* v2A = (const ulonglong2*)vshwA[wid];
        const ulonglong2* v2B = (const ulonglong2*)vshwB[wid];
#pragma unroll
        for (int k2 = 0; k2 < 8; k2++) {
            ulonglong2 qA = v2A[k2];
            ulonglong2 qB = v2B[k2];
            FMA2(cA0, qA.x, eTp[0][2 * k2]);
            FMA2(cB0, qB.x, eTp[0][2 * k2]);
            FMA2(cA1, qA.x, eTp[1][2 * k2]);
            FMA2(cB1, qB.x, eTp[1][2 * k2]);
            FMA2(cA2, qA.x, eTp[2][2 * k2]);
            FMA2(cB2, qB.x, eTp[2][2 * k2]);
            FMA2(cA3, qA.x, eTp[3][2 * k2]);
            FMA2(cB3, qB.x, eTp[3][2 * k2]);
            FMA2(cA0, qA.y, eTp[0][2 * k2 + 1]);
            FMA2(cB0, qB.y, eTp[0][2 * k2 + 1]);
            FMA2(cA1, qA.y, eTp[1][2 * k2 + 1]);
            FMA2(cB1, qB.y, eTp[1][2 * k2 + 1]);
            FMA2(cA2, qA.y, eTp[2][2 * k2 + 1]);
            FMA2(cB2, qB.y, eTp[2][2 * k2 + 1]);
            FMA2(cA3, qA.y, eTp[3][2 * k2 + 1]);
            FMA2(cB3, qB.y, eTp[3][2 * k2 + 1]);
        }
        const int nb = pbuf ^ 1;
        pshA[nb][wid][lane +  0] = hadd2(cA0);
        pshA[nb][wid][lane + 32] = hadd2(cA1);
        pshA[nb][wid][lane + 64] = hadd2(cA2);
        pshA[nb][wid][lane + 96] = hadd2(cA3);
        pshB[nb][wid][lane +  0] = hadd2(cB0);
        pshB[nb][wid][lane + 32] = hadd2(cB1);
        pshB[nb][wid][lane + 64] = hadd2(cB2);
        pshB[nb][wid][lane + 96] = hadd2(cB3);
        if (j == 0) { mshA[nb] = aA_next; mshB[nb] = aB_next; }

        sA_used = sA_prev; eA_used = eA_cur;
        sB_used = sB_prev; eB_used = eB_cur;
        sA_prev = sA_new; sB_prev = sB_new;
        eA_cur = eA_n1; eA_n1 = eA_n2;
        eB_cur = eB_n1; eB_n1 = eB_n2;
        pbuf = nb;
    }

    // ---- per-batch epilogues: exact logsumexp + gold score ----
    const float alphaA = sA_used + __logf(wA) + eA_used;
    const float alphaB = sB_used + __logf(wB) + eB_used;
    const int tags64 = sh_tags64;
    const int mask4 = sh_mask4;

#pragma unroll
    for (int pass = 0; pass < 2; pass++) {
        const float alpha = pass ? alphaB : alphaA;
        const int b = pass ? bB : bA;

        float wm = alpha;
#pragma unroll
        for (int o = 16; o; o >>= 1)
            wm = fmaxf(wm, __shfl_xor_sync(0xffffffffu, wm, o));
        if (lane == 0) warpred[wid] = wm;
        __syncthreads();
        float mx = fmaxf(fmaxf(warpred[0], warpred[1]),
                         fmaxf(warpred[2], warpred[3]));
        float ex = __expf(alpha - mx);
#pragma unroll
        for (int o = 16; o; o >>= 1)
            ex += __shfl_xor_sync(0xffffffffu, ex, o);
        if (lane == 0) warpsum[wid] = ex;
        __syncthreads();
        if (j == 0) {
            float s = (warpsum[0] + warpsum[1]) + (warpsum[2] + warpsum[3]);
            g_part[b] = mx + __logf(s);
        }

        // gold score
        const long long* tg64 = (const long long*)tags_raw + (size_t)b * SS;
        const int* tg32 = (const int*)tags_raw + (size_t)b * SS;
        const int* mk32 = (const int*)mask_raw + (size_t)b * SS;
        const unsigned char* mk8 = (const unsigned char*)mask_raw + (size_t)b * SS;
        const float* em_row = emissions + (size_t)b * SS * NT;

        float g = 0.f;
        for (int t = j; t < SS; t += NT) {
            int tg = tags64 ? (int)tg64[t] : tg32[t];
            int mraw = mask4 ? mk32[t] : (int)mk8[t];
            float mk = mraw ? 1.f : 0.f;
            g += em_row[(size_t)t * NT + tg] * mk;
            if (t > 0) {
                int tp = tags64 ? (int)tg64[t - 1] : tg32[t - 1];
                g += trans[tp * NT + tg] * mk;
            }
        }
#pragma unroll
        for (int o = 16; o; o >>= 1)
            g += __shfl_xor_sync(0xffffffffu, g, o);
        __syncthreads();
        if (lane == 0) warpred[wid] = g;
        __syncthreads();
        if (j == 0)
            g_gold[b] = (warpred[0] + warpred[1]) + (warpred[2] + warpred[3]);
        __syncthreads();
    }
}

// Deterministic final reduction: out = sum_b (part[b] - gold[b]).
__global__ void finish_kernel(float* __restrict__ out) {
    const int b = threadIdx.x;         // 256 threads
    const int lane = b & 31;
    const int wid = b >> 5;
    __shared__ float wsum[8];
    float v = g_part[b] - g_gold[b];
#pragma unroll
    for (int o = 16; o; o >>= 1)
        v += __shfl_xor_sync(0xffffffffu, v, o);
    if (lane == 0) wsum[wid] = v;
    __syncthreads();
    if (b == 0) {
        float s = 0.f;
#pragma unroll
        for (int w = 0; w < 8; w++) s += wsum[w];
        out[0] = s;
    }
}

extern "C" void kernel_launch(void* const* d_in, const int* in_sizes, int n_in,
                              void* d_out, int out_size) {
    const float* emissions = (const float*)d_in[0];
    const void* tags = d_in[1];
    const void* mask = d_in[2];
    const float* trans = (const float*)d_in[3];
    float* out = (float*)d_out;

    crf_forward_kernel<<<BB / 2, NT>>>(emissions, tags, mask, trans);
    finish_kernel<<<1, BB>>>(out);
}

// round 16
// speedup vs baseline: 1.2206x; 1.2206x over previous
#include <cuda_runtime.h>

#define NT 128
#define BB 256
#define SS 512

__device__ float g_part[BB];
__device__ float g_gold[BB];

// ---- packed fp32x2 helpers (sm_100+; ptxas never auto-fuses these) ----
__device__ __forceinline__ unsigned long long pack2(float lo, float hi) {
    unsigned long long r;
    asm("mov.b64 %0, {%1, %2};" : "=l"(r) : "f"(lo), "f"(hi));
    return r;
}
#define FMA2(acc, a, b) \
    asm("fma.rn.f32x2 %0, %1, %2, %0;" : "+l"(acc) : "l"(a), "l"(b))
__device__ __forceinline__ unsigned long long add2(unsigned long long a,
                                                   unsigned long long b) {
    unsigned long long d;
    asm("add.rn.f32x2 %0, %1, %2;" : "=l"(d) : "l"(a), "l"(b));
    return d;
}
__device__ __forceinline__ float hadd2(unsigned long long a) {
    float lo, hi;
    asm("mov.b64 {%0, %1}, %2;" : "=f"(lo), "=f"(hi) : "l"(a));
    return lo + hi;
}

// One CTA per batch, split-K matvec, ONE block barrier per step.
// 2-STALE SHIFT: s_t = alpha_{t-2}[0], so expfac_t = exp((s_{t-1}-s_t)+e_t)
// is precomputed during step t-1's FMA phase -> MUFU off the critical path.
// Post-barrier phase B is only LDS+FADD+FMUL. FMA chains split 16->2x8 deep.
__global__ __launch_bounds__(128, 2) void crf_forward_kernel(
    const float* __restrict__ emissions,      // [B, S, NT]
    const void* __restrict__ tags_raw,        // [B, S] int32 or int64
    const void* __restrict__ mask_raw,        // [B, S] 1B or 4B bool
    const float* __restrict__ trans)          // [NT, NT]
{
    const int b = blockIdx.x;
    const int j = threadIdx.x;
    const int lane = j & 31;
    const int wid = j >> 5;

    __shared__ __align__(16) float vshw[4][32];     // per-warp v slice
    __shared__ __align__(16) float psh[2][4][NT];   // double-buffered partials
    __shared__ float msh[2];                        // alpha[0] pipeline
    __shared__ float warpred[4];
    __shared__ float warpsum[4];
    __shared__ int sh_tags64, sh_mask4;

    // ---- dtype detection (JAX x64-off silently makes int64 -> int32) ----
    if (j == 0) {
        const unsigned int* tw = (const unsigned int*)tags_raw;
        int is64 = 1;
        for (int k = 0; k < 32; k++)
            if (tw[2 * k + 1] != 0u) is64 = 0;
        sh_tags64 = is64;
        unsigned int w0 = ((const unsigned int*)mask_raw)[0];
        sh_mask4 = (w0 & 0xFFFFFF00u) ? 0 : 1;
    }

    // ---- eTp[oi][k]: packed exp(T) for my i-slice x 4 output columns ----
    const int ibase = wid * 32;
    unsigned long long eTp[4][16];
#pragma unroll
    for (int oi = 0; oi < 4; oi++) {
        const int col = lane + 32 * oi;
#pragma unroll
        for (int k = 0; k < 16; k++)
            eTp[oi][k] = pack2(__expf(trans[(ibase + 2 * k) * NT + col]),
                               __expf(trans[(ibase + 2 * k + 1) * NT + col]));
    }

    const float* e_ptr = emissions + (size_t)b * SS * NT;
    float alpha0 = e_ptr[j];           // alpha0 = emissions[b, 0, :]

    if (j == 0) msh[0] = alpha0;       // a0; also serves as s_2 (2-stale)
    __syncthreads();
    const float a0 = msh[0];

    float v_reg = __expf(alpha0 - a0); // v_0  (shift s_0 = a0)

    // shift registers: sm1 = s_{t-1}, s0 = s_t (shift of v being built)
    float sm1 = a0;                    // s_0
    float s0 = a0;                     // s_1 := a0 (free choice)

    // ---- prologue: warp-local exchange of v_0 + phase A -> psh[0] ----
    vshw[wid][lane] = v_reg;
    __syncwarp();
    {
        unsigned long long c0a = 0ull, c1a = 0ull, c2a = 0ull, c3a = 0ull;
        unsigned long long c0b = 0ull, c1b = 0ull, c2b = 0ull, c3b = 0ull;
        const ulonglong2* v2 = (const ulonglong2*)vshw[wid];
#pragma unroll
        for (int k2 = 0; k2 < 4; k2++) {
            ulonglong2 q = v2[k2];
            ulonglong2 r = v2[k2 + 4];
            FMA2(c0a, q.x, eTp[0][2 * k2]);
            FMA2(c1a, q.x, eTp[1][2 * k2]);
            FMA2(c2a, q.x, eTp[2][2 * k2]);
            FMA2(c3a, q.x, eTp[3][2 * k2]);
            FMA2(c0a, q.y, eTp[0][2 * k2 + 1]);
            FMA2(c1a, q.y, eTp[1][2 * k2 + 1]);
            FMA2(c2a, q.y, eTp[2][2 * k2 + 1]);
            FMA2(c3a, q.y, eTp[3][2 * k2 + 1]);
            FMA2(c0b, r.x, eTp[0][2 * k2 + 8]);
            FMA2(c1b, r.x, eTp[1][2 * k2 + 8]);
            FMA2(c2b, r.x, eTp[2][2 * k2 + 8]);
            FMA2(c3b, r.x, eTp[3][2 * k2 + 8]);
            FMA2(c0b, r.y, eTp[0][2 * k2 + 9]);
            FMA2(c1b, r.y, eTp[1][2 * k2 + 9]);
            FMA2(c2b, r.y, eTp[2][2 * k2 + 9]);
            FMA2(c3b, r.y, eTp[3][2 * k2 + 9]);
        }
        psh[0][wid][lane +  0] = hadd2(add2(c0a, c0b));
        psh[0][wid][lane + 32] = hadd2(add2(c1a, c1b));
        psh[0][wid][lane + 64] = hadd2(add2(c2a, c2b));
        psh[0][wid][lane + 96] = hadd2(add2(c3a, c3b));
    }

    // depth-2 emission prefetch: e_cur = row1, e_n1 = row2, e_ptr -> row3
    float e_cur = e_ptr[NT + j];
    float e_n1 = e_ptr[2 * NT + j];
    e_ptr += 3 * NT;

    // expfac for t=1: exp((s_0 - s_1) + e_1) = exp(e_1)
    float expfac = __expf(e_cur);

    float w = 0.f, s_used = 0.f, e_used = 0.f;

    // ---- forward recursion, 511 steps; ONE __syncthreads per step ----
    int pbuf = 0;
    for (int t = 1; t < SS; t++) {
        float e_n2 = 0.f;
        if (t + 2 < SS) { e_n2 = e_ptr[j]; e_ptr += NT; }

        __syncthreads();               // psh[pbuf]/msh[pbuf] visible

        // phase B (short!): assemble w_t, produce v_t with PRE-computed expfac
        float p0 = psh[pbuf][0][j], p1 = psh[pbuf][1][j];
        float p2 = psh[pbuf][2][j], p3 = psh[pbuf][3][j];
        w = (p0 + p1) + (p2 + p3);
        float v_new = w * expfac;

        // off-path: next shift + next expfac (consumed next iteration)
        float sp1 = msh[pbuf];         // s_{t+1} = alpha_{t-1}[0]
        float expfac_next = __expf((s0 - sp1) + e_n1);

        float a_next = 0.f;
        if (j == 0)                    // alpha_t[0] -> shift s_{t+2}
            a_next = sm1 + __logf(w) + e_cur;

        // warp-local v exchange (intra-warp only)
        vshw[wid][lane] = v_new;
        __syncwarp();

        // phase A: partials of w_{t+1}; two 8-deep chains per output
        unsigned long long c0a = 0ull, c1a = 0ull, c2a = 0ull, c3a = 0ull;
        unsigned long long c0b = 0ull, c1b = 0ull, c2b = 0ull, c3b = 0ull;
        const ulonglong2* v2 = (const ulonglong2*)vshw[wid];
#pragma unroll
        for (int k2 = 0; k2 < 4; k2++) {
            ulonglong2 q = v2[k2];
            ulonglong2 r = v2[k2 + 4];
            FMA2(c0a, q.x, eTp[0][2 * k2]);
            FMA2(c1a, q.x, eTp[1][2 * k2]);
            FMA2(c2a, q.x, eTp[2][2 * k2]);
            FMA2(c3a, q.x, eTp[3][2 * k2]);
            FMA2(c0a, q.y, eTp[0][2 * k2 + 1]);
            FMA2(c1a, q.y, eTp[1][2 * k2 + 1]);
            FMA2(c2a, q.y, eTp[2][2 * k2 + 1]);
            FMA2(c3a, q.y, eTp[3][2 * k2 + 1]);
            FMA2(c0b, r.x, eTp[0][2 * k2 + 8]);
            FMA2(c1b, r.x, eTp[1][2 * k2 + 8]);
            FMA2(c2b, r.x, eTp[2][2 * k2 + 8]);
            FMA2(c3b, r.x, eTp[3][2 * k2 + 8]);
            FMA2(c0b, r.y, eTp[0][2 * k2 + 9]);
            FMA2(c1b, r.y, eTp[1][2 * k2 + 9]);
            FMA2(c2b, r.y, eTp[2][2 * k2 + 9]);
            FMA2(c3b, r.y, eTp[3][2 * k2 + 9]);
        }
        const int nb = pbuf ^ 1;
        psh[nb][wid][lane +  0] = hadd2(add2(c0a, c0b));
        psh[nb][wid][lane + 32] = hadd2(add2(c1a, c1b));
        psh[nb][wid][lane + 64] = hadd2(add2(c2a, c2b));
        psh[nb][wid][lane + 96] = hadd2(add2(c3a, c3b));
        if (j == 0) msh[nb] = a_next;

        s_used = sm1; e_used = e_cur;  // alpha_t = sm1 + log(w_t) + e_t
        sm1 = s0;                      // s_t becomes s_{t-1}
        s0 = sp1;                      // s_{t+1} becomes current
        expfac = expfac_next;
        e_cur = e_n1;
        e_n1 = e_n2;
        pbuf = nb;
    }

    // ---- final alpha and exact logsumexp over it ----
    float alpha = s_used + __logf(w) + e_used;
    {
        float wm = alpha;
#pragma unroll
        for (int o = 16; o; o >>= 1)
            wm = fmaxf(wm, __shfl_xor_sync(0xffffffffu, wm, o));
        if (lane == 0) warpred[wid] = wm;
        __syncthreads();
        float mx = fmaxf(fmaxf(warpred[0], warpred[1]),
                         fmaxf(warpred[2], warpred[3]));
        float ex = __expf(alpha - mx);
#pragma unroll
        for (int o = 16; o; o >>= 1)
            ex += __shfl_xor_sync(0xffffffffu, ex, o);
        if (lane == 0) warpsum[wid] = ex;
        __syncthreads();
        if (j == 0) {
            float s = (warpsum[0] + warpsum[1]) + (warpsum[2] + warpsum[3]);
            g_part[b] = mx + __logf(s);
        }
    }

    // ---- gold score for this batch (dtype-adaptive tag/mask reads) ----
    {
        const int tags64 = sh_tags64;   // written in prologue; bars since
        const int mask4 = sh_mask4;
        const long long* tg64 = (const long long*)tags_raw + (size_t)b * SS;
        const int* tg32 = (const int*)tags_raw + (size_t)b * SS;
        const int* mk32 = (const int*)mask_raw + (size_t)b * SS;
        const unsigned char* mk8 = (const unsigned char*)mask_raw + (size_t)b * SS;
        const float* em_row = emissions + (size_t)b * SS * NT;

        float g = 0.f;
        for (int t = j; t < SS; t += NT) {
            int tg = tags64 ? (int)tg64[t] : tg32[t];
            int mraw = mask4 ? mk32[t] : (int)mk8[t];
            float mk = mraw ? 1.f : 0.f;
            g += em_row[(size_t)t * NT + tg] * mk;
            if (t > 0) {
                int tp = tags64 ? (int)tg64[t - 1] : tg32[t - 1];
                g += trans[tp * NT + tg] * mk;
            }
        }
#pragma unroll
        for (int o = 16; o; o >>= 1)
            g += __shfl_xor_sync(0xffffffffu, g, o);
        __syncthreads();   // warpred free for reuse after this
        if (lane == 0) warpred[wid] = g;
        __syncthreads();
        if (j == 0)
            g_gold[b] = (warpred[0] + warpred[1]) + (warpred[2] + warpred[3]);
    }
}

// Deterministic final reduction: out = sum_b (part[b] - gold[b]).
__global__ void finish_kernel(float* __restrict__ out) {
    const int b = threadIdx.x;         // 256 threads
    const int lane = b & 31;
    const int wid = b >> 5;
    __shared__ float wsum[8];
    float v = g_part[b] - g_gold[b];
#pragma unroll
    for (int o = 16; o; o >>= 1)
        v += __shfl_xor_sync(0xffffffffu, v, o);
    if (lane == 0) wsum[wid] = v;
    __syncthreads();
    if (b == 0) {
        float s = 0.f;
#pragma unroll
        for (int w = 0; w < 8; w++) s += wsum[w];
        out[0] = s;
    }
}

extern "C" void kernel_launch(void* const* d_in, const int* in_sizes, int n_in,
                              void* d_out, int out_size) {
    const float* emissions = (const float*)d_in[0];
    const void* tags = d_in[1];
    const void* mask = d_in[2];
    const float* trans = (const float*)d_in[3];
    float* out = (float*)d_out;

    crf_forward_kernel<<<BB, NT>>>(emissions, tags, mask, trans);
    finish_kernel<<<1, BB>>>(out);
}

// round 17
// speedup vs baseline: 1.2403x; 1.0161x over previous
#include <cuda_runtime.h>

#define NT 128
#define BB 256
#define SS 512

__device__ float g_part[BB];
__device__ float g_gold[BB];

// ---- packed fp32x2 helpers (sm_100+; ptxas never auto-fuses these) ----
__device__ __forceinline__ unsigned long long pack2(float lo, float hi) {
    unsigned long long r;
    asm("mov.b64 %0, {%1, %2};" : "=l"(r) : "f"(lo), "f"(hi));
    return r;
}
#define FMA2(acc, a, b) \
    asm("fma.rn.f32x2 %0, %1, %2, %0;" : "+l"(acc) : "l"(a), "l"(b))
__device__ __forceinline__ unsigned long long add2(unsigned long long a,
                                                   unsigned long long b) {
    unsigned long long d;
    asm("add.rn.f32x2 %0, %1, %2;" : "=l"(d) : "l"(a), "l"(b));
    return d;
}
__device__ __forceinline__ float hadd2(unsigned long long a) {
    float lo, hi;
    asm("mov.b64 {%0, %1}, %2;" : "=f"(lo), "=f"(hi) : "l"(a));
    return lo + hi;
}

// One CTA per batch, split-K matvec, ONE block barrier per step.
// 2-stale shift keeps MUFU exp/log off the critical chain; depth-3 emission
// prefetch (~700cyc lookahead) covers DRAM latency at the current step rate.
__global__ __launch_bounds__(128, 2) void crf_forward_kernel(
    const float* __restrict__ emissions,      // [B, S, NT]
    const void* __restrict__ tags_raw,        // [B, S] int32 or int64
    const void* __restrict__ mask_raw,        // [B, S] 1B or 4B bool
    const float* __restrict__ trans)          // [NT, NT]
{
    const int b = blockIdx.x;
    const int j = threadIdx.x;
    const int lane = j & 31;
    const int wid = j >> 5;

    __shared__ __align__(16) float vshw[4][32];     // per-warp v slice
    __shared__ __align__(16) float psh[2][4][NT];   // double-buffered partials
    __shared__ float msh[2];                        // alpha[0] pipeline
    __shared__ float warpred[4];
    __shared__ float warpsum[4];
    __shared__ int sh_tags64, sh_mask4;

    // ---- dtype detection (JAX x64-off silently makes int64 -> int32) ----
    if (j == 0) {
        const unsigned int* tw = (const unsigned int*)tags_raw;
        int is64 = 1;
        for (int k = 0; k < 32; k++)
            if (tw[2 * k + 1] != 0u) is64 = 0;
        sh_tags64 = is64;
        unsigned int w0 = ((const unsigned int*)mask_raw)[0];
        sh_mask4 = (w0 & 0xFFFFFF00u) ? 0 : 1;
    }

    // ---- eTp[oi][k]: packed exp(T) for my i-slice x 4 output columns ----
    const int ibase = wid * 32;
    unsigned long long eTp[4][16];
#pragma unroll
    for (int oi = 0; oi < 4; oi++) {
        const int col = lane + 32 * oi;
#pragma unroll
        for (int k = 0; k < 16; k++)
            eTp[oi][k] = pack2(__expf(trans[(ibase + 2 * k) * NT + col]),
                               __expf(trans[(ibase + 2 * k + 1) * NT + col]));
    }

    const float* e_base = emissions + (size_t)b * SS * NT;
    float alpha0 = e_base[j];          // alpha0 = emissions[b, 0, :]

    if (j == 0) msh[0] = alpha0;       // a0; also serves as s_2 (2-stale)
    __syncthreads();
    const float a0 = msh[0];

    float v_reg = __expf(alpha0 - a0); // v_0  (shift s_0 = a0)

    // shift registers: sm1 = s_{t-1}, s0 = s_t (shift of v being built)
    float sm1 = a0;                    // s_0
    float s0 = a0;                     // s_1 := a0 (free choice)

    // ---- prologue: warp-local exchange of v_0 + phase A -> psh[0] ----
    vshw[wid][lane] = v_reg;
    __syncwarp();
    {
        unsigned long long c0a = 0ull, c1a = 0ull, c2a = 0ull, c3a = 0ull;
        unsigned long long c0b = 0ull, c1b = 0ull, c2b = 0ull, c3b = 0ull;
        const ulonglong2* v2 = (const ulonglong2*)vshw[wid];
#pragma unroll
        for (int k2 = 0; k2 < 4; k2++) {
            ulonglong2 q = v2[k2];
            ulonglong2 r = v2[k2 + 4];
            FMA2(c0a, q.x, eTp[0][2 * k2]);
            FMA2(c1a, q.x, eTp[1][2 * k2]);
            FMA2(c2a, q.x, eTp[2][2 * k2]);
            FMA2(c3a, q.x, eTp[3][2 * k2]);
            FMA2(c0a, q.y, eTp[0][2 * k2 + 1]);
            FMA2(c1a, q.y, eTp[1][2 * k2 + 1]);
            FMA2(c2a, q.y, eTp[2][2 * k2 + 1]);
            FMA2(c3a, q.y, eTp[3][2 * k2 + 1]);
            FMA2(c0b, r.x, eTp[0][2 * k2 + 8]);
            FMA2(c1b, r.x, eTp[1][2 * k2 + 8]);
            FMA2(c2b, r.x, eTp[2][2 * k2 + 8]);
            FMA2(c3b, r.x, eTp[3][2 * k2 + 8]);
            FMA2(c0b, r.y, eTp[0][2 * k2 + 9]);
            FMA2(c1b, r.y, eTp[1][2 * k2 + 9]);
            FMA2(c2b, r.y, eTp[2][2 * k2 + 9]);
            FMA2(c3b, r.y, eTp[3][2 * k2 + 9]);
        }
        psh[0][wid][lane +  0] = hadd2(add2(c0a, c0b));
        psh[0][wid][lane + 32] = hadd2(add2(c1a, c1b));
        psh[0][wid][lane + 64] = hadd2(add2(c2a, c2b));
        psh[0][wid][lane + 96] = hadd2(add2(c3a, c3b));
    }

    // depth-3 emission prefetch: rows t, t+1, t+2 resident
    float e_cur = e_base[1 * NT + j];
    float e_n1 = e_base[2 * NT + j];
    float e_n2 = e_base[3 * NT + j];

    // expfac for t=1: exp((s_0 - s_1) + e_1) = exp(e_1)
    float expfac = __expf(e_cur);

    float w = 0.f, s_used = 0.f, e_used = 0.f;

    // ---- forward recursion, 511 steps; ONE __syncthreads per step ----
    int pbuf = 0;
#pragma unroll 2
    for (int t = 1; t < SS; t++) {
        // depth-3 prefetch, branchless (clamped to last row)
        int tnext = t + 3 < SS - 1 ? t + 3 : SS - 1;
        float e_n3 = e_base[tnext * NT + j];

        __syncthreads();               // psh[pbuf]/msh[pbuf] visible

        // phase B (short): assemble w_t, produce v_t with PRE-computed expfac
        float p0 = psh[pbuf][0][j], p1 = psh[pbuf][1][j];
        float p2 = psh[pbuf][2][j], p3 = psh[pbuf][3][j];
        w = (p0 + p1) + (p2 + p3);
        float v_new = w * expfac;

        // warp-local v exchange FIRST (critical path), MUFUs after
        vshw[wid][lane] = v_new;
        __syncwarp();

        // off-path: next shift + next expfac (consumed next iteration)
        float sp1 = msh[pbuf];         // s_{t+1} = alpha_{t-1}[0]
        float expfac_next = __expf((s0 - sp1) + e_n1);

        float a_next = 0.f;
        if (j == 0)                    // alpha_t[0] -> shift s_{t+2}
            a_next = sm1 + __logf(w) + e_cur;

        // phase A: partials of w_{t+1}; two 8-deep chains per output
        unsigned long long c0a = 0ull, c1a = 0ull, c2a = 0ull, c3a = 0ull;
        unsigned long long c0b = 0ull, c1b = 0ull, c2b = 0ull, c3b = 0ull;
        const ulonglong2* v2 = (const ulonglong2*)vshw[wid];
#pragma unroll
        for (int k2 = 0; k2 < 4; k2++) {
            ulonglong2 q = v2[k2];
            ulonglong2 r = v2[k2 + 4];
            FMA2(c0a, q.x, eTp[0][2 * k2]);
            FMA2(c1a, q.x, eTp[1][2 * k2]);
            FMA2(c2a, q.x, eTp[2][2 * k2]);
            FMA2(c3a, q.x, eTp[3][2 * k2]);
            FMA2(c0a, q.y, eTp[0][2 * k2 + 1]);
            FMA2(c1a, q.y, eTp[1][2 * k2 + 1]);
            FMA2(c2a, q.y, eTp[2][2 * k2 + 1]);
            FMA2(c3a, q.y, eTp[3][2 * k2 + 1]);
            FMA2(c0b, r.x, eTp[0][2 * k2 + 8]);
            FMA2(c1b, r.x, eTp[1][2 * k2 + 8]);
            FMA2(c2b, r.x, eTp[2][2 * k2 + 8]);
            FMA2(c3b, r.x, eTp[3][2 * k2 + 8]);
            FMA2(c0b, r.y, eTp[0][2 * k2 + 9]);
            FMA2(c1b, r.y, eTp[1][2 * k2 + 9]);
            FMA2(c2b, r.y, eTp[2][2 * k2 + 9]);
            FMA2(c3b, r.y, eTp[3][2 * k2 + 9]);
        }
        const int nb = pbuf ^ 1;
        psh[nb][wid][lane +  0] = hadd2(add2(c0a, c0b));
        psh[nb][wid][lane + 32] = hadd2(add2(c1a, c1b));
        psh[nb][wid][lane + 64] = hadd2(add2(c2a, c2b));
        psh[nb][wid][lane + 96] = hadd2(add2(c3a, c3b));
        if (j == 0) msh[nb] = a_next;

        s_used = sm1; e_used = e_cur;  // alpha_t = sm1 + log(w_t) + e_t
        sm1 = s0;                      // s_t becomes s_{t-1}
        s0 = sp1;                      // s_{t+1} becomes current
        expfac = expfac_next;
        e_cur = e_n1;
        e_n1 = e_n2;
        e_n2 = e_n3;
        pbuf = nb;
    }

    // ---- final alpha and exact logsumexp over it ----
    float alpha = s_used + __logf(w) + e_used;
    {
        float wm = alpha;
#pragma unroll
        for (int o = 16; o; o >>= 1)
            wm = fmaxf(wm, __shfl_xor_sync(0xffffffffu, wm, o));
        if (lane == 0) warpred[wid] = wm;
        __syncthreads();
        float mx = fmaxf(fmaxf(warpred[0], warpred[1]),
                         fmaxf(warpred[2], warpred[3]));
        float ex = __expf(alpha - mx);
#pragma unroll
        for (int o = 16; o; o >>= 1)
            ex += __shfl_xor_sync(0xffffffffu, ex, o);
        if (lane == 0) warpsum[wid] = ex;
        __syncthreads();
        if (j == 0) {
            float s = (warpsum[0] + warpsum[1]) + (warpsum[2] + warpsum[3]);
            g_part[b] = mx + __logf(s);
        }
    }

    // ---- gold score for this batch (dtype-adaptive tag/mask reads) ----
    {
        const int tags64 = sh_tags64;   // written in prologue; bars since
        const int mask4 = sh_mask4;
        const long long* tg64 = (const long long*)tags_raw + (size_t)b * SS;
        const int* tg32 = (const int*)tags_raw + (size_t)b * SS;
        const int* mk32 = (const int*)mask_raw + (size_t)b * SS;
        const unsigned char* mk8 = (const unsigned char*)mask_raw + (size_t)b * SS;
        const float* em_row = emissions + (size_t)b * SS * NT;

        float g = 0.f;
        for (int t = j; t < SS; t += NT) {
            int tg = tags64 ? (int)tg64[t] : tg32[t];
            int mraw = mask4 ? mk32[t] : (int)mk8[t];
            float mk = mraw ? 1.f : 0.f;
            g += em_row[(size_t)t * NT + tg] * mk;
            if (t > 0) {
                int tp = tags64 ? (int)tg64[t - 1] : tg32[t - 1];
                g += trans[tp * NT + tg] * mk;
            }
        }
#pragma unroll
        for (int o = 16; o; o >>= 1)
            g += __shfl_xor_sync(0xffffffffu, g, o);
        __syncthreads();   // warpred free for reuse after this
        if (lane == 0) warpred[wid] = g;
        __syncthreads();
        if (j == 0)
            g_gold[b] = (warpred[0] + warpred[1]) + (warpred[2] + warpred[3]);
    }
}

// Deterministic final reduction: out = sum_b (part[b] - gold[b]).
__global__ void finish_kernel(float* __restrict__ out) {
    const int b = threadIdx.x;         // 256 threads
    const int lane = b & 31;
    const int wid = b >> 5;
    __shared__ float wsum[8];
    float v = g_part[b] - g_gold[b];
#pragma unroll
    for (int o = 16; o; o >>= 1)
        v += __shfl_xor_sync(0xffffffffu, v, o);
    if (lane == 0) wsum[wid] = v;
    __syncthreads();
    if (b == 0) {
        float s = 0.f;
#pragma unroll
        for (int w = 0; w < 8; w++) s += wsum[w];
        out[0] = s;
    }
}

extern "C" void kernel_launch(void* const* d_in, const int* in_sizes, int n_in,
                              void* d_out, int out_size) {
    const float* emissions = (const float*)d_in[0];
    const void* tags = d_in[1];
    const void* mask = d_in[2];
    const float* trans = (const float*)d_in[3];
    float* out = (float*)d_out;

    crf_forward_kernel<<<BB, NT>>>(emissions, tags, mask, trans);
    finish_kernel<<<1, BB>>>(out);
}